// round 1
// baseline (speedup 1.0000x reference)
#include <cuda_runtime.h>

#define B  64
#define T  200
#define D  64
#define M  64
#define NS 1000

// ---------------- scratch (device globals; no allocation allowed) ----------------
// w packed as pairs per lane: g_wp[(b*T+t)*32 + lane] = (w[lane], w[lane+32])
__device__ float2 g_wp[B * T * 32];
// (e, a) interleaved: g_ea[(b*T+t)*64 + d]
__device__ float2 g_ea[B * T * D];
// reads: g_read[(b*T+t)*64 + d]
__device__ float  g_read[B * T * D];

__device__ __forceinline__ float sigmoidf_(float x) {
    return 1.0f / (1.0f + __expf(-x));
}

// =====================================================================
// Kernel 1a: w[b,t,:] = softmax(k @ Mk^T)   (gather k = k_emb[skills])
// block = 256 thr (8 warps), 32 rows/block, warp does 4 rows (2 at a time)
// =====================================================================
__global__ __launch_bounds__(256) void k_w(const int* __restrict__ skills,
                                           const float* __restrict__ k_emb,
                                           const float* __restrict__ Mk) {
    __shared__ __align__(16) float Mk_s[64 * 68];     // row stride 68 (LDS.128 conflict-free)
    __shared__ __align__(16) float x_s[8][2][64];

    int tid = threadIdx.x;
    for (int i = tid; i < 64 * 64; i += 256)
        Mk_s[(i >> 6) * 68 + (i & 63)] = Mk[i];
    __syncthreads();

    int w = tid >> 5, l = tid & 31;
    int rbase = blockIdx.x * 32 + w * 4;

    const float* wlp = &Mk_s[l * 68];
    const float* whp = &Mk_s[(l + 32) * 68];

    for (int rp = 0; rp < 2; rp++) {
        int r0 = rbase + rp * 2;
        int s0 = skills[r0];
        int s1 = skills[r0 + 1];
        x_s[w][0][l]      = k_emb[s0 * 64 + l];
        x_s[w][0][l + 32] = k_emb[s0 * 64 + 32 + l];
        x_s[w][1][l]      = k_emb[s1 * 64 + l];
        x_s[w][1][l + 32] = k_emb[s1 * 64 + 32 + l];
        __syncwarp();

        float a00 = 0.f, a01 = 0.f, a10 = 0.f, a11 = 0.f; // [row][out lo/hi]
#pragma unroll
        for (int q = 0; q < 16; q++) {
            float4 xa = *(const float4*)&x_s[w][0][q * 4];
            float4 xb = *(const float4*)&x_s[w][1][q * 4];
            float4 ma = *(const float4*)&wlp[q * 4];
            float4 mb = *(const float4*)&whp[q * 4];
            a00 = fmaf(xa.x, ma.x, a00); a00 = fmaf(xa.y, ma.y, a00);
            a00 = fmaf(xa.z, ma.z, a00); a00 = fmaf(xa.w, ma.w, a00);
            a01 = fmaf(xa.x, mb.x, a01); a01 = fmaf(xa.y, mb.y, a01);
            a01 = fmaf(xa.z, mb.z, a01); a01 = fmaf(xa.w, mb.w, a01);
            a10 = fmaf(xb.x, ma.x, a10); a10 = fmaf(xb.y, ma.y, a10);
            a10 = fmaf(xb.z, ma.z, a10); a10 = fmaf(xb.w, ma.w, a10);
            a11 = fmaf(xb.x, mb.x, a11); a11 = fmaf(xb.y, mb.y, a11);
            a11 = fmaf(xb.z, mb.z, a11); a11 = fmaf(xb.w, mb.w, a11);
        }

        // softmax over 64 outputs (per row), within the warp
        // row 0
        {
            float mx = fmaxf(a00, a01);
#pragma unroll
            for (int o = 16; o; o >>= 1) mx = fmaxf(mx, __shfl_xor_sync(~0u, mx, o));
            float e0 = __expf(a00 - mx), e1 = __expf(a01 - mx);
            float s = e0 + e1;
#pragma unroll
            for (int o = 16; o; o >>= 1) s += __shfl_xor_sync(~0u, s, o);
            float inv = 1.0f / s;
            g_wp[r0 * 32 + l] = make_float2(e0 * inv, e1 * inv);
        }
        // row 1
        {
            float mx = fmaxf(a10, a11);
#pragma unroll
            for (int o = 16; o; o >>= 1) mx = fmaxf(mx, __shfl_xor_sync(~0u, mx, o));
            float e0 = __expf(a10 - mx), e1 = __expf(a11 - mx);
            float s = e0 + e1;
#pragma unroll
            for (int o = 16; o; o >>= 1) s += __shfl_xor_sync(~0u, s, o);
            float inv = 1.0f / s;
            g_wp[(r0 + 1) * 32 + l] = make_float2(e0 * inv, e1 * inv);
        }
        __syncwarp();
    }
}

// =====================================================================
// Kernel 1b: e = sigmoid(v@eW^T+eb), a = tanh(v@aW^T+ab)
// v = v_emb[skills + NS * masked_responses]
// =====================================================================
__global__ __launch_bounds__(256) void k_ea(const int* __restrict__ skills,
                                            const int* __restrict__ responses,
                                            const float* __restrict__ v_emb,
                                            const float* __restrict__ eW,
                                            const float* __restrict__ eb,
                                            const float* __restrict__ aW,
                                            const float* __restrict__ ab) {
    __shared__ __align__(16) float eW_s[64 * 68];
    __shared__ __align__(16) float aW_s[64 * 68];
    __shared__ __align__(16) float x_s[8][2][64];

    int tid = threadIdx.x;
    for (int i = tid; i < 64 * 64; i += 256) {
        eW_s[(i >> 6) * 68 + (i & 63)] = eW[i];
        aW_s[(i >> 6) * 68 + (i & 63)] = aW[i];
    }
    __syncthreads();

    int w = tid >> 5, l = tid & 31;
    int rbase = blockIdx.x * 32 + w * 4;

    const float* ewl = &eW_s[l * 68];
    const float* ewh = &eW_s[(l + 32) * 68];
    const float* awl = &aW_s[l * 68];
    const float* awh = &aW_s[(l + 32) * 68];

    float ebl = eb[l], ebh = eb[l + 32];
    float abl = ab[l], abh = ab[l + 32];

    for (int rp = 0; rp < 2; rp++) {
        int r0 = rbase + rp * 2;
        int sk0 = skills[r0], sk1 = skills[r0 + 1];
        int rs0 = responses[r0], rs1 = responses[r0 + 1];
        int x0 = sk0 + NS * (rs0 > -1 ? rs0 : 0);
        int x1 = sk1 + NS * (rs1 > -1 ? rs1 : 0);
        x_s[w][0][l]      = v_emb[x0 * 64 + l];
        x_s[w][0][l + 32] = v_emb[x0 * 64 + 32 + l];
        x_s[w][1][l]      = v_emb[x1 * 64 + l];
        x_s[w][1][l + 32] = v_emb[x1 * 64 + 32 + l];
        __syncwarp();

        float e00 = 0.f, e01 = 0.f, e10 = 0.f, e11 = 0.f;
        float t00 = 0.f, t01 = 0.f, t10 = 0.f, t11 = 0.f;
#pragma unroll
        for (int q = 0; q < 16; q++) {
            float4 xa = *(const float4*)&x_s[w][0][q * 4];
            float4 xb = *(const float4*)&x_s[w][1][q * 4];
            float4 el4 = *(const float4*)&ewl[q * 4];
            float4 eh4 = *(const float4*)&ewh[q * 4];
            float4 al4 = *(const float4*)&awl[q * 4];
            float4 ah4 = *(const float4*)&awh[q * 4];
            e00 = fmaf(xa.x, el4.x, e00); e00 = fmaf(xa.y, el4.y, e00);
            e00 = fmaf(xa.z, el4.z, e00); e00 = fmaf(xa.w, el4.w, e00);
            e01 = fmaf(xa.x, eh4.x, e01); e01 = fmaf(xa.y, eh4.y, e01);
            e01 = fmaf(xa.z, eh4.z, e01); e01 = fmaf(xa.w, eh4.w, e01);
            e10 = fmaf(xb.x, el4.x, e10); e10 = fmaf(xb.y, el4.y, e10);
            e10 = fmaf(xb.z, el4.z, e10); e10 = fmaf(xb.w, el4.w, e10);
            e11 = fmaf(xb.x, eh4.x, e11); e11 = fmaf(xb.y, eh4.y, e11);
            e11 = fmaf(xb.z, eh4.z, e11); e11 = fmaf(xb.w, eh4.w, e11);
            t00 = fmaf(xa.x, al4.x, t00); t00 = fmaf(xa.y, al4.y, t00);
            t00 = fmaf(xa.z, al4.z, t00); t00 = fmaf(xa.w, al4.w, t00);
            t01 = fmaf(xa.x, ah4.x, t01); t01 = fmaf(xa.y, ah4.y, t01);
            t01 = fmaf(xa.z, ah4.z, t01); t01 = fmaf(xa.w, ah4.w, t01);
            t10 = fmaf(xb.x, al4.x, t10); t10 = fmaf(xb.y, al4.y, t10);
            t10 = fmaf(xb.z, al4.z, t10); t10 = fmaf(xb.w, al4.w, t10);
            t11 = fmaf(xb.x, ah4.x, t11); t11 = fmaf(xb.y, ah4.y, t11);
            t11 = fmaf(xb.z, ah4.z, t11); t11 = fmaf(xb.w, ah4.w, t11);
        }

        g_ea[r0 * 64 + l]            = make_float2(sigmoidf_(e00 + ebl), tanhf(t00 + abl));
        g_ea[r0 * 64 + 32 + l]       = make_float2(sigmoidf_(e01 + ebh), tanhf(t01 + abh));
        g_ea[(r0 + 1) * 64 + l]      = make_float2(sigmoidf_(e10 + ebl), tanhf(t10 + abl));
        g_ea[(r0 + 1) * 64 + 32 + l] = make_float2(sigmoidf_(e11 + ebh), tanhf(t11 + abh));
        __syncwarp();
    }
}

// =====================================================================
// Kernel 2: sequential scan. One warp per (b, d): lane m holds Mv[m,d]
// and Mv[m+32,d]. read BEFORE update. 4096 warps total.
// =====================================================================
__global__ __launch_bounds__(256) void k_scan(const float* __restrict__ Mv0) {
    int wg = blockIdx.x * 8 + (threadIdx.x >> 5);
    int l = threadIdx.x & 31;
    int b = wg >> 6, d = wg & 63;

    float s0 = Mv0[l * 64 + d];
    float s1 = Mv0[(l + 32) * 64 + d];

    const float2* wp = &g_wp[b * T * 32];
    const float2* ea = &g_ea[b * T * 64 + d];
    float*        rd = &g_read[b * T * 64 + d];

#pragma unroll 4
    for (int t = 0; t < T; t++) {
        float2 w2  = wp[t * 32 + l];     // (w[l], w[l+32])  coalesced
        float2 ea2 = ea[t * 64];         // (e[d], a[d])     broadcast
        float r = w2.x * s0 + w2.y * s1; // read uses PRE-update state
        s0 = fmaf(w2.x, fmaf(-ea2.x, s0, ea2.y), s0);
        s1 = fmaf(w2.y, fmaf(-ea2.x, s1, ea2.y), s1);
#pragma unroll
        for (int o = 16; o; o >>= 1) r += __shfl_xor_sync(~0u, r, o);
        if (l == 0) rd[t * 64] = r;
    }
}

// =====================================================================
// Kernel 3: f = tanh([read, k] @ fW^T + fb); p = sigmoid(f @ pW^T + pb)
// output = p[:, 1:]  -> rows are (b, t) with t in [1, 199]
// =====================================================================
__global__ __launch_bounds__(256) void k_out(const int* __restrict__ skills,
                                             const float* __restrict__ k_emb,
                                             const float* __restrict__ fW,
                                             const float* __restrict__ fb,
                                             const float* __restrict__ pW,
                                             const float* __restrict__ pb,
                                             float* __restrict__ out) {
    __shared__ __align__(16) float fW_s[64 * 132];   // [64][128] padded to 132
    __shared__ __align__(16) float x_s[8][2][128];

    int tid = threadIdx.x;
    for (int i = tid; i < 64 * 128; i += 256)
        fW_s[(i >> 7) * 132 + (i & 127)] = fW[i];
    __syncthreads();

    int w = tid >> 5, l = tid & 31;
    int rbase = blockIdx.x * 32 + w * 4;

    const float* wlp = &fW_s[l * 132];
    const float* whp = &fW_s[(l + 32) * 132];
    float fbl = fb[l], fbh = fb[l + 32];
    float pl = pW[l], ph = pW[l + 32];
    float pbv = pb[0];

    for (int rp = 0; rp < 2; rp++) {
        int row0 = rbase + rp * 2;
        int row1 = row0 + 1;
        int b0 = row0 / 199, t0 = row0 % 199 + 1;
        int b1 = row1 / 199, t1 = row1 % 199 + 1;
        int idx0 = b0 * T + t0;
        int idx1 = b1 * T + t1;

        x_s[w][0][l]      = g_read[idx0 * 64 + l];
        x_s[w][0][l + 32] = g_read[idx0 * 64 + 32 + l];
        x_s[w][1][l]      = g_read[idx1 * 64 + l];
        x_s[w][1][l + 32] = g_read[idx1 * 64 + 32 + l];
        int sk0 = skills[idx0], sk1 = skills[idx1];
        x_s[w][0][64 + l] = k_emb[sk0 * 64 + l];
        x_s[w][0][96 + l] = k_emb[sk0 * 64 + 32 + l];
        x_s[w][1][64 + l] = k_emb[sk1 * 64 + l];
        x_s[w][1][96 + l] = k_emb[sk1 * 64 + 32 + l];
        __syncwarp();

        float a00 = fbl, a01 = fbh, a10 = fbl, a11 = fbh;
#pragma unroll
        for (int q = 0; q < 32; q++) {
            float4 xa = *(const float4*)&x_s[w][0][q * 4];
            float4 xb = *(const float4*)&x_s[w][1][q * 4];
            float4 ma = *(const float4*)&wlp[q * 4];
            float4 mb = *(const float4*)&whp[q * 4];
            a00 = fmaf(xa.x, ma.x, a00); a00 = fmaf(xa.y, ma.y, a00);
            a00 = fmaf(xa.z, ma.z, a00); a00 = fmaf(xa.w, ma.w, a00);
            a01 = fmaf(xa.x, mb.x, a01); a01 = fmaf(xa.y, mb.y, a01);
            a01 = fmaf(xa.z, mb.z, a01); a01 = fmaf(xa.w, mb.w, a01);
            a10 = fmaf(xb.x, ma.x, a10); a10 = fmaf(xb.y, ma.y, a10);
            a10 = fmaf(xb.z, ma.z, a10); a10 = fmaf(xb.w, ma.w, a10);
            a11 = fmaf(xb.x, mb.x, a11); a11 = fmaf(xb.y, mb.y, a11);
            a11 = fmaf(xb.z, mb.z, a11); a11 = fmaf(xb.w, mb.w, a11);
        }

        float f00 = tanhf(a00), f01 = tanhf(a01);
        float f10 = tanhf(a10), f11 = tanhf(a11);

        float r0 = f00 * pl + f01 * ph;
        float r1 = f10 * pl + f11 * ph;
#pragma unroll
        for (int o = 16; o; o >>= 1) r0 += __shfl_xor_sync(~0u, r0, o);
#pragma unroll
        for (int o = 16; o; o >>= 1) r1 += __shfl_xor_sync(~0u, r1, o);

        if (l == 0) {
            out[b0 * 199 + (t0 - 1)] = sigmoidf_(r0 + pbv);
            out[b1 * 199 + (t1 - 1)] = sigmoidf_(r1 + pbv);
        }
        __syncwarp();
    }
}

// =====================================================================
// launch
// =====================================================================
extern "C" void kernel_launch(void* const* d_in, const int* in_sizes, int n_in,
                              void* d_out, int out_size) {
    const int*   skills    = (const int*)d_in[0];
    const int*   responses = (const int*)d_in[1];
    const float* k_emb     = (const float*)d_in[2];
    const float* v_emb     = (const float*)d_in[3];
    const float* Mk        = (const float*)d_in[4];
    const float* Mv0       = (const float*)d_in[5];
    const float* fW        = (const float*)d_in[6];
    const float* fb        = (const float*)d_in[7];
    const float* eW        = (const float*)d_in[8];
    const float* eb        = (const float*)d_in[9];
    const float* aW        = (const float*)d_in[10];
    const float* ab        = (const float*)d_in[11];
    const float* pW        = (const float*)d_in[12];
    const float* pb        = (const float*)d_in[13];
    float* out = (float*)d_out;

    k_w  <<<400, 256>>>(skills, k_emb, Mk);
    k_ea <<<400, 256>>>(skills, responses, v_emb, eW, eb, aW, ab);
    k_scan<<<512, 256>>>(Mv0);
    k_out<<<398, 256>>>(skills, k_emb, fW, fb, pW, pb, out);
}

// round 2
// speedup vs baseline: 1.8730x; 1.8730x over previous
#include <cuda_runtime.h>

#define BB 64
#define TT 200
#define NS 1000

// ---------------- device scratch ----------------
__device__ float2 g_Wsk[1000 * 32];   // (w[l], w[l+32]) per skill, softmaxed
__device__ float2 g_EA [2000 * 64];   // (e, a) per x-index, per d
__device__ float2 g_G  [1000 * 32];   // (g[l], g[l+32]) = k·fW2^T + fb
__device__ int    g_idx[BB * TT];     // skill | (x << 16)
__device__ float  g_read[BB * TT * 64];

static __device__ __forceinline__ float tanh_a(float x) {
    float y; asm("tanh.approx.f32 %0, %1;" : "=f"(y) : "f"(x)); return y;
}
static __device__ __forceinline__ float sigmoid_e(float x) {
    return 1.0f / (1.0f + __expf(-x));
}

// =====================================================================
// Kernel P: precompute tables.
//   blocks [0,63):   rows s in [0,1000): Wsk[s] = softmax(k_emb[s]·Mk^T)
//                    G[s] = k_emb[s]·fW2^T + fb
//   blocks [63,188): rows j in [0,2000): EA[j] = (sigmoid(v·eW^T+eb), tanh(v·aW^T+ab))
//   all blocks: first 12800 global threads write g_idx
// =====================================================================
__global__ __launch_bounds__(256) void k_pre(
    const int* __restrict__ skills, const int* __restrict__ responses,
    const float* __restrict__ k_emb, const float* __restrict__ v_emb,
    const float* __restrict__ Mk, const float* __restrict__ fW,
    const float* __restrict__ fb, const float* __restrict__ eW,
    const float* __restrict__ eb, const float* __restrict__ aW,
    const float* __restrict__ ab)
{
    __shared__ __align__(16) float W0[64 * 68];
    __shared__ __align__(16) float W1[64 * 68];
    __shared__ __align__(16) float x_s[8][2][64];

    int tid = threadIdx.x;
    int gt = blockIdx.x * 256 + tid;
    if (gt < BB * TT) {
        int s = skills[gt], r = responses[gt];
        int mr = (r > -1) ? r : 0;
        g_idx[gt] = s | ((s + NS * mr) << 16);
    }

    bool isA = blockIdx.x < 63;
    for (int i = tid; i < 4096; i += 256) {
        int o = i >> 6, q = i & 63;
        W0[o * 68 + q] = isA ? Mk[i] : eW[i];
        W1[o * 68 + q] = isA ? fW[o * 128 + 64 + q] : aW[i];
    }
    __syncthreads();

    int w = tid >> 5, l = tid & 31;
    const float* pL0 = &W0[l * 68];
    const float* pH0 = &W0[(l + 32) * 68];
    const float* pL1 = &W1[l * 68];
    const float* pH1 = &W1[(l + 32) * 68];

    if (isA) {
        int r0 = blockIdx.x * 16 + w * 2;
        if (r0 >= 1000) return;
        *(float2*)&x_s[w][0][2 * l] = *(const float2*)&k_emb[r0 * 64 + 2 * l];
        *(float2*)&x_s[w][1][2 * l] = *(const float2*)&k_emb[(r0 + 1) * 64 + 2 * l];
        __syncwarp();

        float m0l = 0.f, m0h = 0.f, g0l = 0.f, g0h = 0.f;
        float m1l = 0.f, m1h = 0.f, g1l = 0.f, g1h = 0.f;
#pragma unroll
        for (int q = 0; q < 16; q++) {
            float4 xa = *(const float4*)&x_s[w][0][q * 4];
            float4 xb = *(const float4*)&x_s[w][1][q * 4];
            float4 aL = *(const float4*)&pL0[q * 4];
            float4 aH = *(const float4*)&pH0[q * 4];
            float4 bL = *(const float4*)&pL1[q * 4];
            float4 bH = *(const float4*)&pH1[q * 4];
            m0l = fmaf(xa.x, aL.x, m0l); m0l = fmaf(xa.y, aL.y, m0l);
            m0l = fmaf(xa.z, aL.z, m0l); m0l = fmaf(xa.w, aL.w, m0l);
            m0h = fmaf(xa.x, aH.x, m0h); m0h = fmaf(xa.y, aH.y, m0h);
            m0h = fmaf(xa.z, aH.z, m0h); m0h = fmaf(xa.w, aH.w, m0h);
            g0l = fmaf(xa.x, bL.x, g0l); g0l = fmaf(xa.y, bL.y, g0l);
            g0l = fmaf(xa.z, bL.z, g0l); g0l = fmaf(xa.w, bL.w, g0l);
            g0h = fmaf(xa.x, bH.x, g0h); g0h = fmaf(xa.y, bH.y, g0h);
            g0h = fmaf(xa.z, bH.z, g0h); g0h = fmaf(xa.w, bH.w, g0h);
            m1l = fmaf(xb.x, aL.x, m1l); m1l = fmaf(xb.y, aL.y, m1l);
            m1l = fmaf(xb.z, aL.z, m1l); m1l = fmaf(xb.w, aL.w, m1l);
            m1h = fmaf(xb.x, aH.x, m1h); m1h = fmaf(xb.y, aH.y, m1h);
            m1h = fmaf(xb.z, aH.z, m1h); m1h = fmaf(xb.w, aH.w, m1h);
            g1l = fmaf(xb.x, bL.x, g1l); g1l = fmaf(xb.y, bL.y, g1l);
            g1l = fmaf(xb.z, bL.z, g1l); g1l = fmaf(xb.w, bL.w, g1l);
            g1h = fmaf(xb.x, bH.x, g1h); g1h = fmaf(xb.y, bH.y, g1h);
            g1h = fmaf(xb.z, bH.z, g1h); g1h = fmaf(xb.w, bH.w, g1h);
        }
        // softmax row0
        {
            float mx = fmaxf(m0l, m0h);
#pragma unroll
            for (int o = 16; o; o >>= 1) mx = fmaxf(mx, __shfl_xor_sync(~0u, mx, o));
            float e0 = __expf(m0l - mx), e1 = __expf(m0h - mx);
            float s = e0 + e1;
#pragma unroll
            for (int o = 16; o; o >>= 1) s += __shfl_xor_sync(~0u, s, o);
            float inv = 1.0f / s;
            g_Wsk[r0 * 32 + l] = make_float2(e0 * inv, e1 * inv);
        }
        // softmax row1
        {
            float mx = fmaxf(m1l, m1h);
#pragma unroll
            for (int o = 16; o; o >>= 1) mx = fmaxf(mx, __shfl_xor_sync(~0u, mx, o));
            float e0 = __expf(m1l - mx), e1 = __expf(m1h - mx);
            float s = e0 + e1;
#pragma unroll
            for (int o = 16; o; o >>= 1) s += __shfl_xor_sync(~0u, s, o);
            float inv = 1.0f / s;
            g_Wsk[(r0 + 1) * 32 + l] = make_float2(e0 * inv, e1 * inv);
        }
        float fbl = fb[l], fbh = fb[l + 32];
        g_G[r0 * 32 + l]       = make_float2(g0l + fbl, g0h + fbh);
        g_G[(r0 + 1) * 32 + l] = make_float2(g1l + fbl, g1h + fbh);
    } else {
        int j0 = (blockIdx.x - 63) * 16 + w * 2;   // in [0, 2000), exact
        *(float2*)&x_s[w][0][2 * l] = *(const float2*)&v_emb[j0 * 64 + 2 * l];
        *(float2*)&x_s[w][1][2 * l] = *(const float2*)&v_emb[(j0 + 1) * 64 + 2 * l];
        __syncwarp();

        float e0l = 0.f, e0h = 0.f, a0l = 0.f, a0h = 0.f;
        float e1l = 0.f, e1h = 0.f, a1l = 0.f, a1h = 0.f;
#pragma unroll
        for (int q = 0; q < 16; q++) {
            float4 xa = *(const float4*)&x_s[w][0][q * 4];
            float4 xb = *(const float4*)&x_s[w][1][q * 4];
            float4 aL = *(const float4*)&pL0[q * 4];
            float4 aH = *(const float4*)&pH0[q * 4];
            float4 bL = *(const float4*)&pL1[q * 4];
            float4 bH = *(const float4*)&pH1[q * 4];
            e0l = fmaf(xa.x, aL.x, e0l); e0l = fmaf(xa.y, aL.y, e0l);
            e0l = fmaf(xa.z, aL.z, e0l); e0l = fmaf(xa.w, aL.w, e0l);
            e0h = fmaf(xa.x, aH.x, e0h); e0h = fmaf(xa.y, aH.y, e0h);
            e0h = fmaf(xa.z, aH.z, e0h); e0h = fmaf(xa.w, aH.w, e0h);
            a0l = fmaf(xa.x, bL.x, a0l); a0l = fmaf(xa.y, bL.y, a0l);
            a0l = fmaf(xa.z, bL.z, a0l); a0l = fmaf(xa.w, bL.w, a0l);
            a0h = fmaf(xa.x, bH.x, a0h); a0h = fmaf(xa.y, bH.y, a0h);
            a0h = fmaf(xa.z, bH.z, a0h); a0h = fmaf(xa.w, bH.w, a0h);
            e1l = fmaf(xb.x, aL.x, e1l); e1l = fmaf(xb.y, aL.y, e1l);
            e1l = fmaf(xb.z, aL.z, e1l); e1l = fmaf(xb.w, aL.w, e1l);
            e1h = fmaf(xb.x, aH.x, e1h); e1h = fmaf(xb.y, aH.y, e1h);
            e1h = fmaf(xb.z, aH.z, e1h); e1h = fmaf(xb.w, aH.w, e1h);
            a1l = fmaf(xb.x, bL.x, a1l); a1l = fmaf(xb.y, bL.y, a1l);
            a1l = fmaf(xb.z, bL.z, a1l); a1l = fmaf(xb.w, bL.w, a1l);
            a1h = fmaf(xb.x, bH.x, a1h); a1h = fmaf(xb.y, bH.y, a1h);
            a1h = fmaf(xb.z, bH.z, a1h); a1h = fmaf(xb.w, bH.w, a1h);
        }
        float ebl = eb[l], ebh = eb[l + 32];
        float abl = ab[l], abh = ab[l + 32];
        g_EA[j0 * 64 + l]            = make_float2(sigmoid_e(e0l + ebl), tanhf(a0l + abl));
        g_EA[j0 * 64 + l + 32]       = make_float2(sigmoid_e(e0h + ebh), tanhf(a0h + abh));
        g_EA[(j0 + 1) * 64 + l]      = make_float2(sigmoid_e(e1l + ebl), tanhf(a1l + abl));
        g_EA[(j0 + 1) * 64 + l + 32] = make_float2(sigmoid_e(e1h + ebh), tanhf(a1h + abh));
    }
}

// =====================================================================
// Kernel S: sequential scan. warp = (b, d); lane holds Mv[l,d], Mv[l+32,d].
// Reads gathered via tables; read-reduction deferred via smem transpose.
// =====================================================================
__global__ __launch_bounds__(256) void k_scan(const float* __restrict__ Mv0)
{
    __shared__ __align__(16) float buf[8][32][36];

    int w = threadIdx.x >> 5, l = threadIdx.x & 31;
    int wg = blockIdx.x * 8 + w;
    int b = wg >> 6, d = wg & 63;

    float s0 = Mv0[l * 64 + d];
    float s1 = Mv0[(l + 32) * 64 + d];

    const int* idxp = g_idx + b * TT;
    float* rd = g_read + b * TT * 64 + d;
    float (*mybuf)[36] = buf[w];

    for (int c = 0; c < 6; c++) {
        int t0 = c * 32;
        int pk = idxp[t0 + l];
#pragma unroll 8
        for (int j = 0; j < 32; j++) {
            int p = __shfl_sync(0xffffffffu, pk, j);
            int sk = p & 0xffff;
            int xi = p >> 16;
            float2 w2 = g_Wsk[sk * 32 + l];
            float2 ea = g_EA[xi * 64 + d];
            float r = w2.x * s0 + w2.y * s1;          // read BEFORE update
            s0 = fmaf(w2.x, fmaf(-ea.x, s0, ea.y), s0);
            s1 = fmaf(w2.y, fmaf(-ea.x, s1, ea.y), s1);
            mybuf[j][l] = r;
        }
        __syncwarp();
        const float4* rowp = (const float4*)&mybuf[l][0];
        float sum = 0.f;
#pragma unroll
        for (int j = 0; j < 8; j++) {
            float4 v = rowp[j];
            sum += (v.x + v.y) + (v.z + v.w);
        }
        rd[(t0 + l) * 64] = sum;
        __syncwarp();
    }
    // tail: t = 192..199
    {
        int t0 = 192;
        int pk = (l < 8) ? idxp[t0 + l] : 0;
#pragma unroll
        for (int j = 0; j < 8; j++) {
            int p = __shfl_sync(0xffffffffu, pk, j);
            int sk = p & 0xffff;
            int xi = p >> 16;
            float2 w2 = g_Wsk[sk * 32 + l];
            float2 ea = g_EA[xi * 64 + d];
            float r = w2.x * s0 + w2.y * s1;
            s0 = fmaf(w2.x, fmaf(-ea.x, s0, ea.y), s0);
            s1 = fmaf(w2.y, fmaf(-ea.x, s1, ea.y), s1);
            mybuf[j][l] = r;
        }
        __syncwarp();
        if (l < 8) {
            const float4* rowp = (const float4*)&mybuf[l][0];
            float sum = 0.f;
#pragma unroll
            for (int j = 0; j < 8; j++) {
                float4 v = rowp[j];
                sum += (v.x + v.y) + (v.z + v.w);
            }
            rd[(t0 + l) * 64] = sum;
        }
    }
}

// =====================================================================
// Kernel O: p = sigmoid( tanh(read·fW1^T + G[skill]) · pW^T + pb )
// warp = 2 rows; 16 rows/CTA; 796 CTAs (= 12736 rows exactly)
// =====================================================================
__global__ __launch_bounds__(256) void k_out(
    const float* __restrict__ fW, const float* __restrict__ pW,
    const float* __restrict__ pb, float* __restrict__ out)
{
    __shared__ __align__(16) float F1[64 * 68];
    __shared__ __align__(16) float x_s[8][2][64];

    int tid = threadIdx.x;
    for (int i = tid; i < 4096; i += 256) {
        int o = i >> 6, q = i & 63;
        F1[o * 68 + q] = fW[o * 128 + q];
    }
    __syncthreads();

    int w = tid >> 5, l = tid & 31;
    int row0 = blockIdx.x * 16 + w * 2;
    int row1 = row0 + 1;
    int b0 = row0 / 199, t0 = row0 - b0 * 199 + 1;
    int b1 = row1 / 199, t1 = row1 - b1 * 199 + 1;
    int i0 = b0 * TT + t0, i1 = b1 * TT + t1;

    *(float2*)&x_s[w][0][2 * l] = *(const float2*)&g_read[i0 * 64 + 2 * l];
    *(float2*)&x_s[w][1][2 * l] = *(const float2*)&g_read[i1 * 64 + 2 * l];
    __syncwarp();

    const float* pL = &F1[l * 68];
    const float* pH = &F1[(l + 32) * 68];
    float a00 = 0.f, a01 = 0.f, a10 = 0.f, a11 = 0.f;
#pragma unroll
    for (int q = 0; q < 16; q++) {
        float4 xa = *(const float4*)&x_s[w][0][q * 4];
        float4 xb = *(const float4*)&x_s[w][1][q * 4];
        float4 mL = *(const float4*)&pL[q * 4];
        float4 mH = *(const float4*)&pH[q * 4];
        a00 = fmaf(xa.x, mL.x, a00); a00 = fmaf(xa.y, mL.y, a00);
        a00 = fmaf(xa.z, mL.z, a00); a00 = fmaf(xa.w, mL.w, a00);
        a01 = fmaf(xa.x, mH.x, a01); a01 = fmaf(xa.y, mH.y, a01);
        a01 = fmaf(xa.z, mH.z, a01); a01 = fmaf(xa.w, mH.w, a01);
        a10 = fmaf(xb.x, mL.x, a10); a10 = fmaf(xb.y, mL.y, a10);
        a10 = fmaf(xb.z, mL.z, a10); a10 = fmaf(xb.w, mL.w, a10);
        a11 = fmaf(xb.x, mH.x, a11); a11 = fmaf(xb.y, mH.y, a11);
        a11 = fmaf(xb.z, mH.z, a11); a11 = fmaf(xb.w, mH.w, a11);
    }

    int sk0 = g_idx[i0] & 0xffff;
    int sk1 = g_idx[i1] & 0xffff;
    float2 G0 = g_G[sk0 * 32 + l];
    float2 G1 = g_G[sk1 * 32 + l];
    float pl = pW[l], ph = pW[l + 32];

    float f00 = tanh_a(a00 + G0.x), f01 = tanh_a(a01 + G0.y);
    float f10 = tanh_a(a10 + G1.x), f11 = tanh_a(a11 + G1.y);

    float r0 = f00 * pl + f01 * ph;
    float r1 = f10 * pl + f11 * ph;
#pragma unroll
    for (int o = 16; o; o >>= 1) {
        r0 += __shfl_xor_sync(~0u, r0, o);
        r1 += __shfl_xor_sync(~0u, r1, o);
    }
    if (l == 0) {
        float pbv = pb[0];
        out[row0] = sigmoid_e(r0 + pbv);
        out[row1] = sigmoid_e(r1 + pbv);
    }
}

// =====================================================================
// launch
// =====================================================================
extern "C" void kernel_launch(void* const* d_in, const int* in_sizes, int n_in,
                              void* d_out, int out_size) {
    const int*   skills    = (const int*)d_in[0];
    const int*   responses = (const int*)d_in[1];
    const float* k_emb     = (const float*)d_in[2];
    const float* v_emb     = (const float*)d_in[3];
    const float* Mk        = (const float*)d_in[4];
    const float* Mv0       = (const float*)d_in[5];
    const float* fW        = (const float*)d_in[6];
    const float* fb        = (const float*)d_in[7];
    const float* eW        = (const float*)d_in[8];
    const float* eb        = (const float*)d_in[9];
    const float* aW        = (const float*)d_in[10];
    const float* ab        = (const float*)d_in[11];
    const float* pW        = (const float*)d_in[12];
    const float* pb        = (const float*)d_in[13];
    float* out = (float*)d_out;

    k_pre <<<188, 256>>>(skills, responses, k_emb, v_emb, Mk, fW, fb, eW, eb, aW, ab);
    k_scan<<<512, 256>>>(Mv0);
    k_out <<<796, 256>>>(fW, pW, pb, out);
}

// round 3
// speedup vs baseline: 1.8878x; 1.0079x over previous
#include <cuda_runtime.h>

#define BB 64
#define TT 200
#define NS 1000

// ---------------- device scratch ----------------
__device__ float2 g_Wsk[1000 * 32];   // (w[l], w[l+32]) per skill, softmaxed
__device__ float2 g_EA [2000 * 64];   // (e, a) per x-index, per d
__device__ float2 g_G  [1000 * 32];   // (g[l], g[l+32]) = k·fW2^T + fb
__device__ int    g_idx[BB * TT];     // skill | (x << 16)
__device__ float  g_read[BB * TT * 64];

static __device__ __forceinline__ float tanh_a(float x) {
    float y; asm("tanh.approx.f32 %0, %1;" : "=f"(y) : "f"(x)); return y;
}
static __device__ __forceinline__ float sigmoid_e(float x) {
    return 1.0f / (1.0f + __expf(-x));
}

// =====================================================================
// Kernel P: precompute tables. 1 row per warp.
//   blocks [0,125):   skill rows s: Wsk[s]=softmax(k_emb[s]·Mk^T), G[s]=k_emb[s]·fW2^T+fb
//   blocks [125,375): x rows j:     EA[j]=(sigmoid(v·eW^T+eb), tanh(v·aW^T+ab))
//   blocks [0,50): also write g_idx
// =====================================================================
__global__ __launch_bounds__(256) void k_pre(
    const int* __restrict__ skills, const int* __restrict__ responses,
    const float* __restrict__ k_emb, const float* __restrict__ v_emb,
    const float* __restrict__ Mk, const float* __restrict__ fW,
    const float* __restrict__ fb, const float* __restrict__ eW,
    const float* __restrict__ eb, const float* __restrict__ aW,
    const float* __restrict__ ab)
{
    __shared__ __align__(16) float W0[64 * 68];
    __shared__ __align__(16) float W1[64 * 68];
    __shared__ __align__(16) float x_s[8][64];

    int tid = threadIdx.x;
    int gt = blockIdx.x * 256 + tid;
    if (gt < BB * TT) {
        int s = skills[gt], r = responses[gt];
        int mr = (r > -1) ? r : 0;
        g_idx[gt] = s | ((s + NS * mr) << 16);
    }

    bool isA = blockIdx.x < 125;
    for (int i = tid; i < 4096; i += 256) {
        int o = i >> 6, q = i & 63;
        W0[o * 68 + q] = isA ? Mk[i] : eW[i];
        W1[o * 68 + q] = isA ? fW[o * 128 + 64 + q] : aW[i];
    }
    __syncthreads();

    int w = tid >> 5, l = tid & 31;
    const float* pL0 = &W0[l * 68];
    const float* pH0 = &W0[(l + 32) * 68];
    const float* pL1 = &W1[l * 68];
    const float* pH1 = &W1[(l + 32) * 68];
    float* xs = x_s[w];

    if (isA) {
        int r0 = blockIdx.x * 8 + w;             // [0,1000)
        *(float2*)&xs[2 * l] = ((const float2*)&k_emb[r0 * 64])[l];
        __syncwarp();

        float ml = 0.f, mh = 0.f, gl = 0.f, gh = 0.f;
#pragma unroll
        for (int q = 0; q < 16; q++) {
            float4 xa = *(const float4*)&xs[q * 4];
            float4 aL = *(const float4*)&pL0[q * 4];
            float4 aH = *(const float4*)&pH0[q * 4];
            float4 bL = *(const float4*)&pL1[q * 4];
            float4 bH = *(const float4*)&pH1[q * 4];
            ml = fmaf(xa.x, aL.x, ml); ml = fmaf(xa.y, aL.y, ml);
            ml = fmaf(xa.z, aL.z, ml); ml = fmaf(xa.w, aL.w, ml);
            mh = fmaf(xa.x, aH.x, mh); mh = fmaf(xa.y, aH.y, mh);
            mh = fmaf(xa.z, aH.z, mh); mh = fmaf(xa.w, aH.w, mh);
            gl = fmaf(xa.x, bL.x, gl); gl = fmaf(xa.y, bL.y, gl);
            gl = fmaf(xa.z, bL.z, gl); gl = fmaf(xa.w, bL.w, gl);
            gh = fmaf(xa.x, bH.x, gh); gh = fmaf(xa.y, bH.y, gh);
            gh = fmaf(xa.z, bH.z, gh); gh = fmaf(xa.w, bH.w, gh);
        }
        // softmax (logits tiny; skip max-subtraction)
        float e0 = __expf(ml), e1 = __expf(mh);
        float s = e0 + e1;
#pragma unroll
        for (int o = 16; o; o >>= 1) s += __shfl_xor_sync(~0u, s, o);
        float inv = 1.0f / s;
        g_Wsk[r0 * 32 + l] = make_float2(e0 * inv, e1 * inv);
        g_G[r0 * 32 + l]   = make_float2(gl + fb[l], gh + fb[l + 32]);
    } else {
        int j0 = (blockIdx.x - 125) * 8 + w;     // [0,2000)
        *(float2*)&xs[2 * l] = ((const float2*)&v_emb[j0 * 64])[l];
        __syncwarp();

        float el = 0.f, eh = 0.f, al = 0.f, ah = 0.f;
#pragma unroll
        for (int q = 0; q < 16; q++) {
            float4 xa = *(const float4*)&xs[q * 4];
            float4 aL = *(const float4*)&pL0[q * 4];
            float4 aH = *(const float4*)&pH0[q * 4];
            float4 bL = *(const float4*)&pL1[q * 4];
            float4 bH = *(const float4*)&pH1[q * 4];
            el = fmaf(xa.x, aL.x, el); el = fmaf(xa.y, aL.y, el);
            el = fmaf(xa.z, aL.z, el); el = fmaf(xa.w, aL.w, el);
            eh = fmaf(xa.x, aH.x, eh); eh = fmaf(xa.y, aH.y, eh);
            eh = fmaf(xa.z, aH.z, eh); eh = fmaf(xa.w, aH.w, eh);
            al = fmaf(xa.x, bL.x, al); al = fmaf(xa.y, bL.y, al);
            al = fmaf(xa.z, bL.z, al); al = fmaf(xa.w, bL.w, al);
            ah = fmaf(xa.x, bH.x, ah); ah = fmaf(xa.y, bH.y, ah);
            ah = fmaf(xa.z, bH.z, ah); ah = fmaf(xa.w, bH.w, ah);
        }
        g_EA[j0 * 64 + l]      = make_float2(sigmoid_e(el + eb[l]),      tanhf(al + ab[l]));
        g_EA[j0 * 64 + l + 32] = make_float2(sigmoid_e(eh + eb[l + 32]), tanhf(ah + ab[l + 32]));
    }
}

// =====================================================================
// Kernel S: sequential scan, warp = (b,d), 8-deep load prefetch.
// =====================================================================
__global__ __launch_bounds__(256) void k_scan(const float* __restrict__ Mv0)
{
    __shared__ __align__(16) float buf[8][32][36];

    int w = threadIdx.x >> 5, l = threadIdx.x & 31;
    int wg = blockIdx.x * 8 + w;
    int b = wg >> 6, d = wg & 63;

    float s0 = Mv0[l * 64 + d];
    float s1 = Mv0[(l + 32) * 64 + d];

    const int* idxp = g_idx + b * TT;
    float* rd = g_read + b * TT * 64 + d;
    float (*mybuf)[36] = buf[w];

    int pk = idxp[l];                           // chunk 0 indices
    for (int c = 0; c < 6; c++) {
        int t0 = c * 32;
        int pknext = (c < 5) ? idxp[t0 + 32 + l]
                             : ((l < 8) ? idxp[192 + l] : 0);

        float2 w2b[8], eab[8];
#pragma unroll
        for (int j = 0; j < 8; j++) {
            int p = __shfl_sync(0xffffffffu, pk, j);
            w2b[j] = g_Wsk[(p & 0xffff) * 32 + l];
            eab[j] = g_EA[(p >> 16) * 64 + d];
        }
#pragma unroll
        for (int j = 0; j < 32; j++) {
            float2 w2 = w2b[j & 7];
            float2 ea = eab[j & 7];
            if (j < 24) {
                int p = __shfl_sync(0xffffffffu, pk, j + 8);
                w2b[j & 7] = g_Wsk[(p & 0xffff) * 32 + l];
                eab[j & 7] = g_EA[(p >> 16) * 64 + d];
            }
            float r = w2.x * s0 + w2.y * s1;    // read BEFORE update
            s0 = fmaf(w2.x, fmaf(-ea.x, s0, ea.y), s0);
            s1 = fmaf(w2.y, fmaf(-ea.x, s1, ea.y), s1);
            mybuf[j][l] = r;
        }
        __syncwarp();
        const float4* rowp = (const float4*)&mybuf[l][0];
        float sum = 0.f;
#pragma unroll
        for (int j = 0; j < 8; j++) {
            float4 v = rowp[j];
            sum += (v.x + v.y) + (v.z + v.w);
        }
        rd[(t0 + l) * 64] = sum;
        __syncwarp();
        pk = pknext;
    }
    // tail: t = 192..199 (indices already in pk, lanes 0..7)
    {
        float2 w2b[8], eab[8];
#pragma unroll
        for (int j = 0; j < 8; j++) {
            int p = __shfl_sync(0xffffffffu, pk, j);
            w2b[j] = g_Wsk[(p & 0xffff) * 32 + l];
            eab[j] = g_EA[(p >> 16) * 64 + d];
        }
#pragma unroll
        for (int j = 0; j < 8; j++) {
            float2 w2 = w2b[j];
            float2 ea = eab[j];
            float r = w2.x * s0 + w2.y * s1;
            s0 = fmaf(w2.x, fmaf(-ea.x, s0, ea.y), s0);
            s1 = fmaf(w2.y, fmaf(-ea.x, s1, ea.y), s1);
            mybuf[j][l] = r;
        }
        __syncwarp();
        if (l < 8) {
            const float4* rowp = (const float4*)&mybuf[l][0];
            float sum = 0.f;
#pragma unroll
            for (int j = 0; j < 8; j++) {
                float4 v = rowp[j];
                sum += (v.x + v.y) + (v.z + v.w);
            }
            rd[(192 + l) * 64] = sum;
        }
    }
}

// =====================================================================
// Kernel O: p = sigmoid( tanh(read·fW1^T + G[skill]) · pW^T + pb )
// 32 rows/block; 398 blocks (12736 rows exactly)
// =====================================================================
__global__ __launch_bounds__(256) void k_out(
    const float* __restrict__ fW, const float* __restrict__ pW,
    const float* __restrict__ pb, float* __restrict__ out)
{
    __shared__ __align__(16) float F1[64 * 68];
    __shared__ __align__(16) float x_s[8][2][64];

    int tid = threadIdx.x;
    for (int i = tid; i < 4096; i += 256) {
        int o = i >> 6, q = i & 63;
        F1[o * 68 + q] = fW[o * 128 + q];
    }
    __syncthreads();

    int w = tid >> 5, l = tid & 31;
    const float* pL = &F1[l * 68];
    const float* pH = &F1[(l + 32) * 68];
    float pl = pW[l], ph = pW[l + 32];
    float pbv = pb[0];

    for (int rp = 0; rp < 2; rp++) {
        int row0 = blockIdx.x * 32 + w * 4 + rp * 2;
        int row1 = row0 + 1;
        int b0 = row0 / 199, t0 = row0 - b0 * 199 + 1;
        int b1 = row1 / 199, t1 = row1 - b1 * 199 + 1;
        int i0 = b0 * TT + t0, i1 = b1 * TT + t1;

        *(float2*)&x_s[w][0][2 * l] = ((const float2*)&g_read[i0 * 64])[l];
        *(float2*)&x_s[w][1][2 * l] = ((const float2*)&g_read[i1 * 64])[l];
        __syncwarp();

        float a00 = 0.f, a01 = 0.f, a10 = 0.f, a11 = 0.f;
#pragma unroll
        for (int q = 0; q < 16; q++) {
            float4 xa = *(const float4*)&x_s[w][0][q * 4];
            float4 xb = *(const float4*)&x_s[w][1][q * 4];
            float4 mL = *(const float4*)&pL[q * 4];
            float4 mH = *(const float4*)&pH[q * 4];
            a00 = fmaf(xa.x, mL.x, a00); a00 = fmaf(xa.y, mL.y, a00);
            a00 = fmaf(xa.z, mL.z, a00); a00 = fmaf(xa.w, mL.w, a00);
            a01 = fmaf(xa.x, mH.x, a01); a01 = fmaf(xa.y, mH.y, a01);
            a01 = fmaf(xa.z, mH.z, a01); a01 = fmaf(xa.w, mH.w, a01);
            a10 = fmaf(xb.x, mL.x, a10); a10 = fmaf(xb.y, mL.y, a10);
            a10 = fmaf(xb.z, mL.z, a10); a10 = fmaf(xb.w, mL.w, a10);
            a11 = fmaf(xb.x, mH.x, a11); a11 = fmaf(xb.y, mH.y, a11);
            a11 = fmaf(xb.z, mH.z, a11); a11 = fmaf(xb.w, mH.w, a11);
        }

        int sk0 = g_idx[i0] & 0xffff;
        int sk1 = g_idx[i1] & 0xffff;
        float2 G0 = g_G[sk0 * 32 + l];
        float2 G1 = g_G[sk1 * 32 + l];

        float f00 = tanh_a(a00 + G0.x), f01 = tanh_a(a01 + G0.y);
        float f10 = tanh_a(a10 + G1.x), f11 = tanh_a(a11 + G1.y);

        float r0 = f00 * pl + f01 * ph;
        float r1 = f10 * pl + f11 * ph;
#pragma unroll
        for (int o = 16; o; o >>= 1) {
            r0 += __shfl_xor_sync(~0u, r0, o);
            r1 += __shfl_xor_sync(~0u, r1, o);
        }
        if (l == 0) {
            out[row0] = sigmoid_e(r0 + pbv);
            out[row1] = sigmoid_e(r1 + pbv);
        }
        __syncwarp();
    }
}

// =====================================================================
// launch
// =====================================================================
extern "C" void kernel_launch(void* const* d_in, const int* in_sizes, int n_in,
                              void* d_out, int out_size) {
    const int*   skills    = (const int*)d_in[0];
    const int*   responses = (const int*)d_in[1];
    const float* k_emb     = (const float*)d_in[2];
    const float* v_emb     = (const float*)d_in[3];
    const float* Mk        = (const float*)d_in[4];
    const float* Mv0       = (const float*)d_in[5];
    const float* fW        = (const float*)d_in[6];
    const float* fb        = (const float*)d_in[7];
    const float* eW        = (const float*)d_in[8];
    const float* eb        = (const float*)d_in[9];
    const float* aW        = (const float*)d_in[10];
    const float* ab        = (const float*)d_in[11];
    const float* pW        = (const float*)d_in[12];
    const float* pb        = (const float*)d_in[13];
    float* out = (float*)d_out;

    k_pre <<<375, 256>>>(skills, responses, k_emb, v_emb, Mk, fW, fb, eW, eb, aW, ab);
    k_scan<<<512, 256>>>(Mv0);
    k_out <<<398, 256>>>(fW, pW, pb, out);
}